// round 15
// baseline (speedup 1.0000x reference)
#include <cuda_runtime.h>
#include <cstdint>
#include <math.h>

typedef unsigned long long u64;

#define NB   4096
#define NL   50
#define NT   64
#define NF   3
#define NH   20
#define NG   80
#define NO   16
#define NSEQ (NB*NL)        // 204800
#define TPB  64
#define NQUAD (NSEQ/4)      // 51200
#define NCTA_L (NQUAD/TPB)  // 800
#define CONV_GRID 296       // 148 SMs x 2 CTAs, persistent over batches

// ---------------- device scratch (static; zero-initialized at load) -------------
__device__ int   g_hist[64];
__device__ int   g_off[64];
__device__ int   g_order[NSEQ];
__device__ float g_hout[(size_t)NSEQ * NH];

// ---------------- packed f32x2 helpers ------------------------------------------
__device__ __forceinline__ u64 f2pack(float lo, float hi) {
    u64 r; asm("mov.b64 %0, {%1, %2};" : "=l"(r) : "f"(lo), "f"(hi)); return r;
}
__device__ __forceinline__ void f2unpack(u64 v, float& lo, float& hi) {
    asm("mov.b64 {%0, %1}, %2;" : "=f"(lo), "=f"(hi) : "l"(v));
}
__device__ __forceinline__ u64 ffma2(u64 a, u64 b, u64 c) {
    u64 d; asm("fma.rn.f32x2 %0, %1, %2, %3;" : "=l"(d) : "l"(a), "l"(b), "l"(c)); return d;
}
__device__ __forceinline__ u64 mul2(u64 a, u64 b) {
    u64 r; asm("mul.rn.f32x2 %0, %1, %2;" : "=l"(r) : "l"(a), "l"(b)); return r;
}
__device__ __forceinline__ float tanhaf(float a) {
    float r; asm("tanh.approx.f32 %0, %1;" : "=f"(r) : "f"(a)); return r;
}
// packed tanh: 2 scalar MUFU.TANH
__device__ __forceinline__ u64 tanh2(u64 a) {
    float a0, a1; f2unpack(a, a0, a1);
    return f2pack(tanhaf(a0), tanhaf(a1));
}

// accurate sigmoid (conv stage only)
__device__ __forceinline__ float fsig(float v) {
    return __fdividef(1.0f, 1.0f + __expf(-v));
}

// ---------------- counting sort, descending length, 3 launches -------------------
__global__ void k_hist(const int* __restrict__ lengths) {
    __shared__ int sh[64];
    if (threadIdx.x < 64) sh[threadIdx.x] = 0;
    __syncthreads();
    int i = blockIdx.x * 256 + threadIdx.x;
    if (i < NSEQ) atomicAdd(&sh[lengths[i] & 63], 1);
    __syncthreads();
    if (threadIdx.x < 64 && sh[threadIdx.x]) atomicAdd(&g_hist[threadIdx.x], sh[threadIdx.x]);
}
__global__ void k_scan() {
    if (threadIdx.x == 0) {
        int acc = 0;
        #pragma unroll
        for (int i = 63; i >= 0; --i) { int v = g_hist[i]; g_off[i] = acc; acc += v; }
    }
    __syncthreads();
    if (threadIdx.x < 64) g_hist[threadIdx.x] = 0;   // deterministic on graph replay
}
__global__ void k_scatter(const int* __restrict__ lengths) {
    __shared__ int sh[64], base[64];
    if (threadIdx.x < 64) sh[threadIdx.x] = 0;
    __syncthreads();
    int i = blockIdx.x * 256 + threadIdx.x, l = 0, r = 0;
    if (i < NSEQ) { l = lengths[i] & 63; r = atomicAdd(&sh[l], 1); }
    __syncthreads();
    if (threadIdx.x < 64) {
        int c = sh[threadIdx.x];
        if (c) base[threadIdx.x] = atomicAdd(&g_off[threadIdx.x], c);
    }
    __syncthreads();
    if (i < NSEQ) g_order[base[l] + r] = i;
}

// ---------------- LSTM: frozen R9 configuration (proven optimum) -----------------
#define ACC2(accA, accB, wbase) do {                                           \
    const ulonglong2* wp_ = (const ulonglong2*)(wbase);                        \
    ulonglong2 w_;                                                             \
    w_ = wp_[0];                                                               \
    accA = ffma2(hA0,  w_.x, accA); accB = ffma2(hB0,  w_.x, accB);            \
    accA = ffma2(hA1,  w_.y, accA); accB = ffma2(hB1,  w_.y, accB);            \
    w_ = wp_[1];                                                               \
    accA = ffma2(hA2,  w_.x, accA); accB = ffma2(hB2,  w_.x, accB);            \
    accA = ffma2(hA3,  w_.y, accA); accB = ffma2(hB3,  w_.y, accB);            \
    w_ = wp_[2];                                                               \
    accA = ffma2(hA4,  w_.x, accA); accB = ffma2(hB4,  w_.x, accB);            \
    accA = ffma2(hA5,  w_.y, accA); accB = ffma2(hB5,  w_.y, accB);            \
    w_ = wp_[3];                                                               \
    accA = ffma2(hA6,  w_.x, accA); accB = ffma2(hB6,  w_.x, accB);            \
    accA = ffma2(hA7,  w_.y, accA); accB = ffma2(hB7,  w_.y, accB);            \
    w_ = wp_[4];                                                               \
    accA = ffma2(hA8,  w_.x, accA); accB = ffma2(hB8,  w_.x, accB);            \
    accA = ffma2(hA9,  w_.y, accA); accB = ffma2(hB9,  w_.y, accB);            \
    w_ = wp_[5];                                                               \
    accA = ffma2(hA10, w_.x, accA); accB = ffma2(hB10, w_.x, accB);            \
    accA = ffma2(hA11, w_.y, accA); accB = ffma2(hB11, w_.y, accB);            \
    w_ = wp_[6];                                                               \
    accA = ffma2(hA12, w_.x, accA); accB = ffma2(hB12, w_.x, accB);            \
    accA = ffma2(hA13, w_.y, accA); accB = ffma2(hB13, w_.y, accB);            \
    w_ = wp_[7];                                                               \
    accA = ffma2(hA14, w_.x, accA); accB = ffma2(hB14, w_.x, accB);            \
    accA = ffma2(hA15, w_.y, accA); accB = ffma2(hB15, w_.y, accB);            \
    w_ = wp_[8];                                                               \
    accA = ffma2(hA16, w_.x, accA); accB = ffma2(hB16, w_.x, accB);            \
    accA = ffma2(hA17, w_.y, accA); accB = ffma2(hB17, w_.y, accB);            \
    w_ = wp_[9];                                                               \
    accA = ffma2(hA18, w_.x, accA); accB = ffma2(hB18, w_.x, accB);            \
    accA = ffma2(hA19, w_.y, accA); accB = ffma2(hB19, w_.y, accB);            \
} while (0)

#define SNAP(P, SEL, dst) do { float lo_, hi_;                                 \
    f2unpack(P##0,  lo_, hi_); (dst)[0]  = SEL;                                \
    f2unpack(P##1,  lo_, hi_); (dst)[1]  = SEL;                                \
    f2unpack(P##2,  lo_, hi_); (dst)[2]  = SEL;                                \
    f2unpack(P##3,  lo_, hi_); (dst)[3]  = SEL;                                \
    f2unpack(P##4,  lo_, hi_); (dst)[4]  = SEL;                                \
    f2unpack(P##5,  lo_, hi_); (dst)[5]  = SEL;                                \
    f2unpack(P##6,  lo_, hi_); (dst)[6]  = SEL;                                \
    f2unpack(P##7,  lo_, hi_); (dst)[7]  = SEL;                                \
    f2unpack(P##8,  lo_, hi_); (dst)[8]  = SEL;                                \
    f2unpack(P##9,  lo_, hi_); (dst)[9]  = SEL;                                \
    f2unpack(P##10, lo_, hi_); (dst)[10] = SEL;                                \
    f2unpack(P##11, lo_, hi_); (dst)[11] = SEL;                                \
    f2unpack(P##12, lo_, hi_); (dst)[12] = SEL;                                \
    f2unpack(P##13, lo_, hi_); (dst)[13] = SEL;                                \
    f2unpack(P##14, lo_, hi_); (dst)[14] = SEL;                                \
    f2unpack(P##15, lo_, hi_); (dst)[15] = SEL;                                \
    f2unpack(P##16, lo_, hi_); (dst)[16] = SEL;                                \
    f2unpack(P##17, lo_, hi_); (dst)[17] = SEL;                                \
    f2unpack(P##18, lo_, hi_); (dst)[18] = SEL;                                \
    f2unpack(P##19, lo_, hi_); (dst)[19] = SEL;                                \
} while (0)

__global__ void __launch_bounds__(TPB)
k_lstm(const float* __restrict__ x, const int* __restrict__ lengths,
       const float* __restrict__ w_ih, const float* __restrict__ w_hh,
       const float* __restrict__ b_ih, const float* __restrict__ b_hh)
{
    __shared__ __align__(16) u64 sWhh2[NH * 4 * NH];       // 12800 B
    __shared__ __align__(16) u64 sC[NH * 16];              //  2560 B
    __shared__ __align__(16) ulonglong2 cbuf[NH * TPB];    // 20480 B
    __shared__ __align__(16) ulonglong2 hnbuf[NH * TPB];   // 20480 B

    const int tid = threadIdx.x;

    // weight folding for MUFU.TANH activations:
    //   sigma(v) = 0.5 + 0.5*tanh(0.5 v)  -> fold 0.5 into i,f,o rows
    //   tanh(v)  -> g rows unchanged
    for (int i = tid; i < NH * 4 * NH; i += TPB) {
        int j = i / 80, g = (i / 20) & 3, k = i % 20;
        float fold = (g == 2) ? 1.0f : 0.5f;
        float w = w_hh[(g * 20 + j) * 20 + k] * fold;
        sWhh2[i] = f2pack(w, w);
    }
    for (int i = tid; i < NH * 16; i += TPB) {
        int j = i >> 4, e = i & 15;
        float w;
        if (e < 4) {
            int r = e * 20 + j;
            float fold = (e == 2) ? 1.0f : 0.5f;
            w = (b_ih[r] + b_hh[r]) * fold;
        } else {
            int g = (e - 4) / 3, k = (e - 4) % 3;
            float fold = (g == 2) ? 1.0f : 0.5f;
            w = w_ih[(g * 20 + j) * 3 + k] * fold;
        }
        sC[i] = f2pack(w, w);
    }
    #pragma unroll
    for (int j = 0; j < NH; ++j) cbuf[j * TPB + tid] = make_ulonglong2(0ull, 0ull);
    __syncthreads();

    const int qid = blockIdx.x * TPB + tid;
    const int s0 = g_order[4 * qid + 0];
    const int s1 = g_order[4 * qid + 1];
    const int s2 = g_order[4 * qid + 2];
    const int s3 = g_order[4 * qid + 3];
    const int len0 = lengths[s0], len1 = lengths[s1];
    const int len2 = lengths[s2], len3 = lengths[s3];
    const int tmax = max(max(len0, len1), max(len2, len3));

    const float* p0 = x + (size_t)s0 * (NT * NF);
    const float* p1 = x + (size_t)s1 * (NT * NF);
    const float* p2 = x + (size_t)s2 * (NT * NF);
    const float* p3 = x + (size_t)s3 * (NT * NF);

    const u64 HALF2 = f2pack(0.5f, 0.5f);

    u64 hA0 = 0, hA1 = 0, hA2 = 0, hA3 = 0, hA4 = 0, hA5 = 0, hA6 = 0, hA7 = 0,
        hA8 = 0, hA9 = 0, hA10 = 0, hA11 = 0, hA12 = 0, hA13 = 0, hA14 = 0,
        hA15 = 0, hA16 = 0, hA17 = 0, hA18 = 0, hA19 = 0;
    u64 hB0 = 0, hB1 = 0, hB2 = 0, hB3 = 0, hB4 = 0, hB5 = 0, hB6 = 0, hB7 = 0,
        hB8 = 0, hB9 = 0, hB10 = 0, hB11 = 0, hB12 = 0, hB13 = 0, hB14 = 0,
        hB15 = 0, hB16 = 0, hB17 = 0, hB18 = 0, hB19 = 0;

    u64 xA0 = 0, xA1 = 0, xA2 = 0, xB0 = 0, xB1 = 0, xB2 = 0;
    if (tmax > 0) {
        xA0 = f2pack(p0[0], p1[0]); xA1 = f2pack(p0[1], p1[1]); xA2 = f2pack(p0[2], p1[2]);
        xB0 = f2pack(p2[0], p3[0]); xB1 = f2pack(p2[1], p3[1]); xB2 = f2pack(p2[2], p3[2]);
    }

    for (int t = 0; t < tmax; ++t) {
        const int tn = min(t + 1, NT - 1);
        const u64 nA0 = f2pack(p0[3 * tn + 0], p1[3 * tn + 0]);
        const u64 nA1 = f2pack(p0[3 * tn + 1], p1[3 * tn + 1]);
        const u64 nA2 = f2pack(p0[3 * tn + 2], p1[3 * tn + 2]);
        const u64 nB0 = f2pack(p2[3 * tn + 0], p3[3 * tn + 0]);
        const u64 nB1 = f2pack(p2[3 * tn + 1], p3[3 * tn + 1]);
        const u64 nB2 = f2pack(p2[3 * tn + 2], p3[3 * tn + 2]);

        #pragma unroll 2
        for (int j = 0; j < NH; ++j) {
            const ulonglong2* cb_ = (const ulonglong2*)(sC + j * 16);
            const ulonglong2 b01 = cb_[0], b23 = cb_[1];
            const ulonglong2 wa = cb_[2], wb = cb_[3], wc = cb_[4];
            const ulonglong2 wd = cb_[5], we = cb_[6], wf = cb_[7];

            u64 aiA = b01.x, afA = b01.y, agA = b23.x, aoA = b23.y;
            u64 aiB = b01.x, afB = b01.y, agB = b23.x, aoB = b23.y;

            aiA = ffma2(xA0, wa.x, aiA); aiB = ffma2(xB0, wa.x, aiB);
            aiA = ffma2(xA1, wa.y, aiA); aiB = ffma2(xB1, wa.y, aiB);
            aiA = ffma2(xA2, wb.x, aiA); aiB = ffma2(xB2, wb.x, aiB);
            afA = ffma2(xA0, wb.y, afA); afB = ffma2(xB0, wb.y, afB);
            afA = ffma2(xA1, wc.x, afA); afB = ffma2(xB1, wc.x, afB);
            afA = ffma2(xA2, wc.y, afA); afB = ffma2(xB2, wc.y, afB);
            agA = ffma2(xA0, wd.x, agA); agB = ffma2(xB0, wd.x, agB);
            agA = ffma2(xA1, wd.y, agA); agB = ffma2(xB1, wd.y, agB);
            agA = ffma2(xA2, we.x, agA); agB = ffma2(xB2, we.x, agB);
            aoA = ffma2(xA0, we.y, aoA); aoB = ffma2(xB0, we.y, aoB);
            aoA = ffma2(xA1, wf.x, aoA); aoB = ffma2(xB1, wf.x, aoB);
            aoA = ffma2(xA2, wf.y, aoA); aoB = ffma2(xB2, wf.y, aoB);

            ACC2(aiA, aiB, sWhh2 + j * 80);
            ACC2(afA, afB, sWhh2 + j * 80 + 20);
            ACC2(agA, agB, sWhh2 + j * 80 + 40);
            ACC2(aoA, aoB, sWhh2 + j * 80 + 60);

            const ulonglong2 cold = cbuf[j * TPB + tid];
            ulonglong2 cnew, hnew;

            {
                u64 si = ffma2(tanh2(aiA), HALF2, HALF2);
                u64 sf = ffma2(tanh2(afA), HALF2, HALF2);
                u64 tg = tanh2(agA);
                u64 so = ffma2(tanh2(aoA), HALF2, HALF2);
                u64 cn = ffma2(sf, cold.x, mul2(si, tg));
                cnew.x = cn;
                hnew.x = mul2(so, tanh2(cn));
            }
            {
                u64 si = ffma2(tanh2(aiB), HALF2, HALF2);
                u64 sf = ffma2(tanh2(afB), HALF2, HALF2);
                u64 tg = tanh2(agB);
                u64 so = ffma2(tanh2(aoB), HALF2, HALF2);
                u64 cn = ffma2(sf, cold.y, mul2(si, tg));
                cnew.y = cn;
                hnew.y = mul2(so, tanh2(cn));
            }

            cbuf[j * TPB + tid]  = cnew;
            hnbuf[j * TPB + tid] = hnew;
        }

        #define RELOAD(k) { ulonglong2 v_ = hnbuf[(k) * TPB + tid]; hA##k = v_.x; hB##k = v_.y; }
        RELOAD(0)  RELOAD(1)  RELOAD(2)  RELOAD(3)  RELOAD(4)
        RELOAD(5)  RELOAD(6)  RELOAD(7)  RELOAD(8)  RELOAD(9)
        RELOAD(10) RELOAD(11) RELOAD(12) RELOAD(13) RELOAD(14)
        RELOAD(15) RELOAD(16) RELOAD(17) RELOAD(18) RELOAD(19)
        #undef RELOAD

        const int tp1 = t + 1;
        if (tp1 == len0) { float* d = g_hout + (size_t)s0 * NH; SNAP(hA, lo_, d); }
        if (tp1 == len1) { float* d = g_hout + (size_t)s1 * NH; SNAP(hA, hi_, d); }
        if (tp1 == len2) { float* d = g_hout + (size_t)s2 * NH; SNAP(hB, lo_, d); }
        if (tp1 == len3) { float* d = g_hout + (size_t)s3 * NH; SNAP(hB, hi_, d); }

        xA0 = nA0; xA1 = nA1; xA2 = nA2;
        xB0 = nB0; xB1 = nB1; xB2 = nB2;
    }
}

// ---------------- conv + FC: persistent CTAs, all weights staged once ------------
#define C1OUT 46
#define C2OUT 22
#define C3OUT 19
// dynamic smem layout (float offsets)
#define CO_W1   0                    // 2560
#define CO_W2   2560                 // 4096
#define CO_W3   6656                 // 4096
#define CO_FW   10752                // 9728 (fc1)
#define CO_FEAT 20480                // 800
#define CO_Y1   21280                // 1472
#define CO_Y2   22752                // 704
#define CO_Y3   23456                // 608
#define CO_SH   24064                // 1000
#define CO_SWL  25064                // 320
#define CO_SBL  25384                // 16
#define CO_SFC  25400                // 16
#define CO_LEN  25416                // 50 (ints)
#define CONV_SMEM_FLOATS 25472
#define CONV_SMEM_BYTES  (CONV_SMEM_FLOATS * 4)   // 101888 B -> 2 CTAs/SM

__global__ void __launch_bounds__(128)
k_conv(const int* __restrict__ lengths,
       const float* __restrict__ w_lin, const float* __restrict__ b_lin,
       const float* __restrict__ c1_w, const float* __restrict__ c1_b,
       const float* __restrict__ c2_w, const float* __restrict__ c2_b,
       const float* __restrict__ c3_w, const float* __restrict__ c3_b,
       const float* __restrict__ fc1_w, const float* __restrict__ fc1_b,
       const float* __restrict__ fc2_w, const float* __restrict__ fc2_b,
       float* __restrict__ out)
{
    extern __shared__ __align__(16) float csm[];
    float* w1   = csm + CO_W1;
    float* w2   = csm + CO_W2;
    float* w3   = csm + CO_W3;
    float* fw   = csm + CO_FW;
    float* feat = csm + CO_FEAT;
    float* y1   = csm + CO_Y1;
    float* y2   = csm + CO_Y2;
    float* y3   = csm + CO_Y3;
    float* sh   = csm + CO_SH;
    float* swl  = csm + CO_SWL;
    float* sbl  = csm + CO_SBL;
    float* sfc  = csm + CO_SFC;
    int*   slen = (int*)(csm + CO_LEN);

    const int tid = threadIdx.x;

    // stage ALL weights once per persistent CTA
    for (int i = tid; i < 2560; i += 128) w1[i] = c1_w[i];
    for (int i = tid; i < 4096; i += 128) w2[i] = c2_w[i];
    for (int i = tid; i < 4096; i += 128) w3[i] = c3_w[i];
    for (int i = tid; i < 9728; i += 128) fw[i] = fc1_w[i];
    for (int i = tid; i < NO * NH; i += 128) swl[i] = w_lin[i];
    if (tid < NO) sbl[tid] = b_lin[tid];

    for (int b = blockIdx.x; b < NB; b += CONV_GRID) {
        __syncthreads();   // weights staged (first iter) / prior batch done

        if (tid < NL) slen[tid] = lengths[b * NL + tid];
        __syncthreads();
        for (int i = tid; i < NL * NH; i += 128) {
            int l = i / NH, k = i % NH;
            sh[i] = (slen[l] > 0) ? g_hout[(size_t)(b * NL + l) * NH + k] : 0.0f;
        }
        __syncthreads();

        // layer summary
        for (int i = tid; i < NO * NL; i += 128) {
            int c = i / NL, l = i % NL;
            float s = sbl[c];
            #pragma unroll
            for (int k = 0; k < NH; ++k) s += sh[l * NH + k] * swl[c * NH + k];
            feat[c * NL + l] = (slen[l] > 0) ? fsig(s) : 0.0f;
        }
        __syncthreads();

        // conv1: 16ch k5 s1 -> [32][46]; 4 positions/thread
        for (int idx = tid; idx < 32 * 12; idx += 128) {
            int o = idx / 12, pg = idx % 12, pp = pg * 4;
            float a0 = c1_b[o], a1 = a0, a2 = a0, a3 = a0;
            #pragma unroll
            for (int c = 0; c < 16; ++c) {
                const float* f = feat + c * 50 + pp;
                const float* w = w1 + (o * 16 + c) * 5;
                float wv0 = w[0], wv1 = w[1], wv2 = w[2], wv3 = w[3], wv4 = w[4];
                float f0 = f[0], f1 = f[1], f2 = f[2], f3 = f[3];
                float f4 = f[4], f5 = f[5], f6 = f[6], f7 = f[7];
                a0 += f0*wv0 + f1*wv1 + f2*wv2 + f3*wv3 + f4*wv4;
                a1 += f1*wv0 + f2*wv1 + f3*wv2 + f4*wv3 + f5*wv4;
                a2 += f2*wv0 + f3*wv1 + f4*wv2 + f5*wv3 + f6*wv4;
                a3 += f3*wv0 + f4*wv1 + f5*wv2 + f6*wv3 + f7*wv4;
            }
            if (pp + 0 < C1OUT) y1[o * C1OUT + pp + 0] = fmaxf(a0, 0.0f);
            if (pp + 1 < C1OUT) y1[o * C1OUT + pp + 1] = fmaxf(a1, 0.0f);
            if (pp + 2 < C1OUT) y1[o * C1OUT + pp + 2] = fmaxf(a2, 0.0f);
            if (pp + 3 < C1OUT) y1[o * C1OUT + pp + 3] = fmaxf(a3, 0.0f);
        }
        __syncthreads();

        // conv2: 32ch k4 s2 -> [32][22]
        for (int idx = tid; idx < 32 * 6; idx += 128) {
            int o = idx / 6, pg = idx % 6, pp = pg * 4;
            float a0 = c2_b[o], a1 = a0, a2 = a0, a3 = a0;
            #pragma unroll
            for (int c = 0; c < 32; ++c) {
                const float* f = y1 + c * C1OUT + 2 * pp;
                const float* w = w2 + (o * 32 + c) * 4;
                float wv0 = w[0], wv1 = w[1], wv2 = w[2], wv3 = w[3];
                float f0 = f[0], f1 = f[1], f2 = f[2], f3 = f[3], f4 = f[4];
                float f5 = f[5], f6 = f[6], f7 = f[7], f8 = f[8], f9 = f[9];
                a0 += f0*wv0 + f1*wv1 + f2*wv2 + f3*wv3;
                a1 += f2*wv0 + f3*wv1 + f4*wv2 + f5*wv3;
                a2 += f4*wv0 + f5*wv1 + f6*wv2 + f7*wv3;
                a3 += f6*wv0 + f7*wv1 + f8*wv2 + f9*wv3;
            }
            if (pp + 0 < C2OUT) y2[o * C2OUT + pp + 0] = fmaxf(a0, 0.0f);
            if (pp + 1 < C2OUT) y2[o * C2OUT + pp + 1] = fmaxf(a1, 0.0f);
            if (pp + 2 < C2OUT) y2[o * C2OUT + pp + 2] = fmaxf(a2, 0.0f);
            if (pp + 3 < C2OUT) y2[o * C2OUT + pp + 3] = fmaxf(a3, 0.0f);
        }
        __syncthreads();

        // conv3: 32ch k4 s1 -> [32][19]
        for (int idx = tid; idx < 32 * 5; idx += 128) {
            int o = idx / 5, pg = idx % 5, pp = pg * 4;
            float a0 = c3_b[o], a1 = a0, a2 = a0, a3 = a0;
            #pragma unroll
            for (int c = 0; c < 32; ++c) {
                const float* f = y2 + c * C2OUT + pp;
                const float* w = w3 + (o * 32 + c) * 4;
                float wv0 = w[0], wv1 = w[1], wv2 = w[2], wv3 = w[3];
                float f0 = f[0], f1 = f[1], f2 = f[2], f3 = f[3];
                float f4 = f[4], f5 = f[5], f6 = f[6];
                a0 += f0*wv0 + f1*wv1 + f2*wv2 + f3*wv3;
                a1 += f1*wv0 + f2*wv1 + f3*wv2 + f4*wv3;
                a2 += f2*wv0 + f3*wv1 + f4*wv2 + f5*wv3;
                a3 += f3*wv0 + f4*wv1 + f5*wv2 + f6*wv3;
            }
            if (pp + 0 < C3OUT) y3[o * C3OUT + pp + 0] = fmaxf(a0, 0.0f);
            if (pp + 1 < C3OUT) y3[o * C3OUT + pp + 1] = fmaxf(a1, 0.0f);
            if (pp + 2 < C3OUT) y3[o * C3OUT + pp + 2] = fmaxf(a2, 0.0f);
            if (pp + 3 < C3OUT) y3[o * C3OUT + pp + 3] = fmaxf(a3, 0.0f);
        }
        __syncthreads();

        // fc1: [16,608] @ y3 (weights now in shared), shuffle reduce
        {
            const int wd = tid >> 5, lane = tid & 31;
            for (int o = wd; o < 16; o += 4) {
                float a = 0.0f;
                const float* w = fw + o * 608;
                for (int k = lane; k < 608; k += 32) a += y3[k] * w[k];
                #pragma unroll
                for (int s = 16; s > 0; s >>= 1) a += __shfl_xor_sync(0xffffffffu, a, s);
                if (lane == 0) sfc[o] = fmaxf(a + fc1_b[o], 0.0f);
            }
        }
        __syncthreads();

        // fc2: [4,16]
        if (tid < 4) {
            float a = fc2_b[tid];
            #pragma unroll
            for (int k = 0; k < 16; ++k) a += sfc[k] * fc2_w[tid * 16 + k];
            out[(size_t)b * 4 + tid] = a;
        }
    }
}

// ---------------- launch ----------------------------------------------------------
extern "C" void kernel_launch(void* const* d_in, const int* in_sizes, int n_in,
                              void* d_out, int out_size)
{
    const float* x       = (const float*)d_in[0];
    const int*   lengths = (const int*)  d_in[1];
    const float* w_ih    = (const float*)d_in[2];
    const float* w_hh    = (const float*)d_in[3];
    const float* b_ih    = (const float*)d_in[4];
    const float* b_hh    = (const float*)d_in[5];
    const float* w_lin   = (const float*)d_in[6];
    const float* b_lin   = (const float*)d_in[7];
    const float* c1_w    = (const float*)d_in[8];
    const float* c1_b    = (const float*)d_in[9];
    const float* c2_w    = (const float*)d_in[10];
    const float* c2_b    = (const float*)d_in[11];
    const float* c3_w    = (const float*)d_in[12];
    const float* c3_b    = (const float*)d_in[13];
    const float* fc1_w   = (const float*)d_in[14];
    const float* fc1_b   = (const float*)d_in[15];
    const float* fc2_w   = (const float*)d_in[16];
    const float* fc2_b   = (const float*)d_in[17];
    float* out = (float*)d_out;

    // idempotent, non-stream op (safe under graph capture)
    cudaFuncSetAttribute(k_conv, cudaFuncAttributeMaxDynamicSharedMemorySize,
                         CONV_SMEM_BYTES);

    k_hist<<<(NSEQ + 255) / 256, 256>>>(lengths);
    k_scan<<<1, 64>>>();
    k_scatter<<<(NSEQ + 255) / 256, 256>>>(lengths);

    k_lstm<<<NCTA_L, TPB>>>(x, lengths, w_ih, w_hh, b_ih, b_hh);

    k_conv<<<CONV_GRID, 128, CONV_SMEM_BYTES>>>(
        lengths, w_lin, b_lin, c1_w, c1_b, c2_w, c2_b, c3_w, c3_b,
        fc1_w, fc1_b, fc2_w, fc2_b, out);
}

// round 16
// speedup vs baseline: 1.0268x; 1.0268x over previous
#include <cuda_runtime.h>
#include <cstdint>
#include <math.h>

typedef unsigned long long u64;

#define NB   4096
#define NL   50
#define NT   64
#define NF   3
#define NH   20
#define NG   80
#define NO   16
#define NSEQ (NB*NL)        // 204800
#define TPB  64
#define NQUAD (NSEQ/4)      // 51200
#define NCTA_L (NQUAD/TPB)  // 800

// ---------------- device scratch (static; zero-initialized at load) -------------
__device__ int   g_hist[64];
__device__ int   g_off[64];
__device__ int   g_order[NSEQ];
__device__ float g_hout[(size_t)NSEQ * NH];

// ---------------- packed f32x2 helpers ------------------------------------------
__device__ __forceinline__ u64 f2pack(float lo, float hi) {
    u64 r; asm("mov.b64 %0, {%1, %2};" : "=l"(r) : "f"(lo), "f"(hi)); return r;
}
__device__ __forceinline__ void f2unpack(u64 v, float& lo, float& hi) {
    asm("mov.b64 {%0, %1}, %2;" : "=f"(lo), "=f"(hi) : "l"(v));
}
__device__ __forceinline__ u64 ffma2(u64 a, u64 b, u64 c) {
    u64 d; asm("fma.rn.f32x2 %0, %1, %2, %3;" : "=l"(d) : "l"(a), "l"(b), "l"(c)); return d;
}
__device__ __forceinline__ u64 mul2(u64 a, u64 b) {
    u64 r; asm("mul.rn.f32x2 %0, %1, %2;" : "=l"(r) : "l"(a), "l"(b)); return r;
}
__device__ __forceinline__ float tanhaf(float a) {
    float r; asm("tanh.approx.f32 %0, %1;" : "=f"(r) : "f"(a)); return r;
}
// packed tanh: 2 scalar MUFU.TANH
__device__ __forceinline__ u64 tanh2(u64 a) {
    float a0, a1; f2unpack(a, a0, a1);
    return f2pack(tanhaf(a0), tanhaf(a1));
}

// accurate sigmoid (conv stage only)
__device__ __forceinline__ float fsig(float v) {
    return __fdividef(1.0f, 1.0f + __expf(-v));
}

// ---------------- counting sort, descending length, 3 launches -------------------
__global__ void k_hist(const int* __restrict__ lengths) {
    __shared__ int sh[64];
    if (threadIdx.x < 64) sh[threadIdx.x] = 0;
    __syncthreads();
    int i = blockIdx.x * 256 + threadIdx.x;
    if (i < NSEQ) atomicAdd(&sh[lengths[i] & 63], 1);
    __syncthreads();
    if (threadIdx.x < 64 && sh[threadIdx.x]) atomicAdd(&g_hist[threadIdx.x], sh[threadIdx.x]);
}
__global__ void k_scan() {
    if (threadIdx.x == 0) {
        int acc = 0;
        #pragma unroll
        for (int i = 63; i >= 0; --i) { int v = g_hist[i]; g_off[i] = acc; acc += v; }
    }
    __syncthreads();
    if (threadIdx.x < 64) g_hist[threadIdx.x] = 0;   // deterministic on graph replay
}
__global__ void k_scatter(const int* __restrict__ lengths) {
    __shared__ int sh[64], base[64];
    if (threadIdx.x < 64) sh[threadIdx.x] = 0;
    __syncthreads();
    int i = blockIdx.x * 256 + threadIdx.x, l = 0, r = 0;
    if (i < NSEQ) { l = lengths[i] & 63; r = atomicAdd(&sh[l], 1); }
    __syncthreads();
    if (threadIdx.x < 64) {
        int c = sh[threadIdx.x];
        if (c) base[threadIdx.x] = atomicAdd(&g_off[threadIdx.x], c);
    }
    __syncthreads();
    if (i < NSEQ) g_order[base[l] + r] = i;
}

// ---------------- LSTM: 4 seqs/thread, half-folded weights, MUFU.TANH ------------
#define ACC2(accA, accB, wbase) do {                                           \
    const ulonglong2* wp_ = (const ulonglong2*)(wbase);                        \
    ulonglong2 w_;                                                             \
    w_ = wp_[0];                                                               \
    accA = ffma2(hA0,  w_.x, accA); accB = ffma2(hB0,  w_.x, accB);            \
    accA = ffma2(hA1,  w_.y, accA); accB = ffma2(hB1,  w_.y, accB);            \
    w_ = wp_[1];                                                               \
    accA = ffma2(hA2,  w_.x, accA); accB = ffma2(hB2,  w_.x, accB);            \
    accA = ffma2(hA3,  w_.y, accA); accB = ffma2(hB3,  w_.y, accB);            \
    w_ = wp_[2];                                                               \
    accA = ffma2(hA4,  w_.x, accA); accB = ffma2(hB4,  w_.x, accB);            \
    accA = ffma2(hA5,  w_.y, accA); accB = ffma2(hB5,  w_.y, accB);            \
    w_ = wp_[3];                                                               \
    accA = ffma2(hA6,  w_.x, accA); accB = ffma2(hB6,  w_.x, accB);            \
    accA = ffma2(hA7,  w_.y, accA); accB = ffma2(hB7,  w_.y, accB);            \
    w_ = wp_[4];                                                               \
    accA = ffma2(hA8,  w_.x, accA); accB = ffma2(hB8,  w_.x, accB);            \
    accA = ffma2(hA9,  w_.y, accA); accB = ffma2(hB9,  w_.y, accB);            \
    w_ = wp_[5];                                                               \
    accA = ffma2(hA10, w_.x, accA); accB = ffma2(hB10, w_.x, accB);            \
    accA = ffma2(hA11, w_.y, accA); accB = ffma2(hB11, w_.y, accB);            \
    w_ = wp_[6];                                                               \
    accA = ffma2(hA12, w_.x, accA); accB = ffma2(hB12, w_.x, accB);            \
    accA = ffma2(hA13, w_.y, accA); accB = ffma2(hB13, w_.y, accB);            \
    w_ = wp_[7];                                                               \
    accA = ffma2(hA14, w_.x, accA); accB = ffma2(hB14, w_.x, accB);            \
    accA = ffma2(hA15, w_.y, accA); accB = ffma2(hB15, w_.y, accB);            \
    w_ = wp_[8];                                                               \
    accA = ffma2(hA16, w_.x, accA); accB = ffma2(hB16, w_.x, accB);            \
    accA = ffma2(hA17, w_.y, accA); accB = ffma2(hB17, w_.y, accB);            \
    w_ = wp_[9];                                                               \
    accA = ffma2(hA18, w_.x, accA); accB = ffma2(hB18, w_.x, accB);            \
    accA = ffma2(hA19, w_.y, accA); accB = ffma2(hB19, w_.y, accB);            \
} while (0)

#define SNAP(P, SEL, dst) do { float lo_, hi_;                                 \
    f2unpack(P##0,  lo_, hi_); (dst)[0]  = SEL;                                \
    f2unpack(P##1,  lo_, hi_); (dst)[1]  = SEL;                                \
    f2unpack(P##2,  lo_, hi_); (dst)[2]  = SEL;                                \
    f2unpack(P##3,  lo_, hi_); (dst)[3]  = SEL;                                \
    f2unpack(P##4,  lo_, hi_); (dst)[4]  = SEL;                                \
    f2unpack(P##5,  lo_, hi_); (dst)[5]  = SEL;                                \
    f2unpack(P##6,  lo_, hi_); (dst)[6]  = SEL;                                \
    f2unpack(P##7,  lo_, hi_); (dst)[7]  = SEL;                                \
    f2unpack(P##8,  lo_, hi_); (dst)[8]  = SEL;                                \
    f2unpack(P##9,  lo_, hi_); (dst)[9]  = SEL;                                \
    f2unpack(P##10, lo_, hi_); (dst)[10] = SEL;                                \
    f2unpack(P##11, lo_, hi_); (dst)[11] = SEL;                                \
    f2unpack(P##12, lo_, hi_); (dst)[12] = SEL;                                \
    f2unpack(P##13, lo_, hi_); (dst)[13] = SEL;                                \
    f2unpack(P##14, lo_, hi_); (dst)[14] = SEL;                                \
    f2unpack(P##15, lo_, hi_); (dst)[15] = SEL;                                \
    f2unpack(P##16, lo_, hi_); (dst)[16] = SEL;                                \
    f2unpack(P##17, lo_, hi_); (dst)[17] = SEL;                                \
    f2unpack(P##18, lo_, hi_); (dst)[18] = SEL;                                \
    f2unpack(P##19, lo_, hi_); (dst)[19] = SEL;                                \
} while (0)

__global__ void __launch_bounds__(TPB)
k_lstm(const float* __restrict__ x, const int* __restrict__ lengths,
       const float* __restrict__ w_ih, const float* __restrict__ w_hh,
       const float* __restrict__ b_ih, const float* __restrict__ b_hh)
{
    __shared__ __align__(16) u64 sWhh2[NH * 4 * NH];       // 12800 B
    __shared__ __align__(16) u64 sC[NH * 16];              //  2560 B
    __shared__ __align__(16) ulonglong2 cbuf[NH * TPB];    // 20480 B
    __shared__ __align__(16) ulonglong2 hnbuf[NH * TPB];   // 20480 B

    const int tid = threadIdx.x;

    // weight folding for MUFU.TANH activations:
    //   sigma(v) = 0.5 + 0.5*tanh(0.5 v)  -> fold 0.5 into i,f,o rows
    //   tanh(v)  -> g rows unchanged
    for (int i = tid; i < NH * 4 * NH; i += TPB) {
        int j = i / 80, g = (i / 20) & 3, k = i % 20;
        float fold = (g == 2) ? 1.0f : 0.5f;
        float w = w_hh[(g * 20 + j) * 20 + k] * fold;
        sWhh2[i] = f2pack(w, w);
    }
    for (int i = tid; i < NH * 16; i += TPB) {
        int j = i >> 4, e = i & 15;
        float w;
        if (e < 4) {
            int r = e * 20 + j;
            float fold = (e == 2) ? 1.0f : 0.5f;
            w = (b_ih[r] + b_hh[r]) * fold;
        } else {
            int g = (e - 4) / 3, k = (e - 4) % 3;
            float fold = (g == 2) ? 1.0f : 0.5f;
            w = w_ih[(g * 20 + j) * 3 + k] * fold;
        }
        sC[i] = f2pack(w, w);
    }
    #pragma unroll
    for (int j = 0; j < NH; ++j) cbuf[j * TPB + tid] = make_ulonglong2(0ull, 0ull);
    __syncthreads();

    const int qid = blockIdx.x * TPB + tid;
    const int s0 = g_order[4 * qid + 0];
    const int s1 = g_order[4 * qid + 1];
    const int s2 = g_order[4 * qid + 2];
    const int s3 = g_order[4 * qid + 3];
    const int len0 = lengths[s0], len1 = lengths[s1];
    const int len2 = lengths[s2], len3 = lengths[s3];
    const int tmax = max(max(len0, len1), max(len2, len3));

    const float* p0 = x + (size_t)s0 * (NT * NF);
    const float* p1 = x + (size_t)s1 * (NT * NF);
    const float* p2 = x + (size_t)s2 * (NT * NF);
    const float* p3 = x + (size_t)s3 * (NT * NF);

    const u64 HALF2 = f2pack(0.5f, 0.5f);

    u64 hA0 = 0, hA1 = 0, hA2 = 0, hA3 = 0, hA4 = 0, hA5 = 0, hA6 = 0, hA7 = 0,
        hA8 = 0, hA9 = 0, hA10 = 0, hA11 = 0, hA12 = 0, hA13 = 0, hA14 = 0,
        hA15 = 0, hA16 = 0, hA17 = 0, hA18 = 0, hA19 = 0;
    u64 hB0 = 0, hB1 = 0, hB2 = 0, hB3 = 0, hB4 = 0, hB5 = 0, hB6 = 0, hB7 = 0,
        hB8 = 0, hB9 = 0, hB10 = 0, hB11 = 0, hB12 = 0, hB13 = 0, hB14 = 0,
        hB15 = 0, hB16 = 0, hB17 = 0, hB18 = 0, hB19 = 0;

    u64 xA0 = 0, xA1 = 0, xA2 = 0, xB0 = 0, xB1 = 0, xB2 = 0;
    if (tmax > 0) {
        xA0 = f2pack(p0[0], p1[0]); xA1 = f2pack(p0[1], p1[1]); xA2 = f2pack(p0[2], p1[2]);
        xB0 = f2pack(p2[0], p3[0]); xB1 = f2pack(p2[1], p3[1]); xB2 = f2pack(p2[2], p3[2]);
    }

    for (int t = 0; t < tmax; ++t) {
        const int tn = min(t + 1, NT - 1);
        const u64 nA0 = f2pack(p0[3 * tn + 0], p1[3 * tn + 0]);
        const u64 nA1 = f2pack(p0[3 * tn + 1], p1[3 * tn + 1]);
        const u64 nA2 = f2pack(p0[3 * tn + 2], p1[3 * tn + 2]);
        const u64 nB0 = f2pack(p2[3 * tn + 0], p3[3 * tn + 0]);
        const u64 nB1 = f2pack(p2[3 * tn + 1], p3[3 * tn + 1]);
        const u64 nB2 = f2pack(p2[3 * tn + 2], p3[3 * tn + 2]);

        #pragma unroll 2
        for (int j = 0; j < NH; ++j) {
            const ulonglong2* cb_ = (const ulonglong2*)(sC + j * 16);
            const ulonglong2 b01 = cb_[0], b23 = cb_[1];
            const ulonglong2 wa = cb_[2], wb = cb_[3], wc = cb_[4];
            const ulonglong2 wd = cb_[5], we = cb_[6], wf = cb_[7];

            u64 aiA = b01.x, afA = b01.y, agA = b23.x, aoA = b23.y;
            u64 aiB = b01.x, afB = b01.y, agB = b23.x, aoB = b23.y;

            aiA = ffma2(xA0, wa.x, aiA); aiB = ffma2(xB0, wa.x, aiB);
            aiA = ffma2(xA1, wa.y, aiA); aiB = ffma2(xB1, wa.y, aiB);
            aiA = ffma2(xA2, wb.x, aiA); aiB = ffma2(xB2, wb.x, aiB);
            afA = ffma2(xA0, wb.y, afA); afB = ffma2(xB0, wb.y, afB);
            afA = ffma2(xA1, wc.x, afA); afB = ffma2(xB1, wc.x, afB);
            afA = ffma2(xA2, wc.y, afA); afB = ffma2(xB2, wc.y, afB);
            agA = ffma2(xA0, wd.x, agA); agB = ffma2(xB0, wd.x, agB);
            agA = ffma2(xA1, wd.y, agA); agB = ffma2(xB1, wd.y, agB);
            agA = ffma2(xA2, we.x, agA); agB = ffma2(xB2, we.x, agB);
            aoA = ffma2(xA0, we.y, aoA); aoB = ffma2(xB0, we.y, aoB);
            aoA = ffma2(xA1, wf.x, aoA); aoB = ffma2(xB1, wf.x, aoB);
            aoA = ffma2(xA2, wf.y, aoA); aoB = ffma2(xB2, wf.y, aoB);

            ACC2(aiA, aiB, sWhh2 + j * 80);
            ACC2(afA, afB, sWhh2 + j * 80 + 20);
            ACC2(agA, agB, sWhh2 + j * 80 + 40);
            ACC2(aoA, aoB, sWhh2 + j * 80 + 60);

            const ulonglong2 cold = cbuf[j * TPB + tid];
            ulonglong2 cnew, hnew;

            // pack A: sigma = 0.5 + 0.5*tanh(folded), tanh direct (MUFU.TANH)
            {
                u64 si = ffma2(tanh2(aiA), HALF2, HALF2);
                u64 sf = ffma2(tanh2(afA), HALF2, HALF2);
                u64 tg = tanh2(agA);
                u64 so = ffma2(tanh2(aoA), HALF2, HALF2);
                u64 cn = ffma2(sf, cold.x, mul2(si, tg));
                cnew.x = cn;
                hnew.x = mul2(so, tanh2(cn));
            }
            // pack B
            {
                u64 si = ffma2(tanh2(aiB), HALF2, HALF2);
                u64 sf = ffma2(tanh2(afB), HALF2, HALF2);
                u64 tg = tanh2(agB);
                u64 so = ffma2(tanh2(aoB), HALF2, HALF2);
                u64 cn = ffma2(sf, cold.y, mul2(si, tg));
                cnew.y = cn;
                hnew.y = mul2(so, tanh2(cn));
            }

            cbuf[j * TPB + tid]  = cnew;
            hnbuf[j * TPB + tid] = hnew;
        }

        // commit h from staging into named regs
        #define RELOAD(k) { ulonglong2 v_ = hnbuf[(k) * TPB + tid]; hA##k = v_.x; hB##k = v_.y; }
        RELOAD(0)  RELOAD(1)  RELOAD(2)  RELOAD(3)  RELOAD(4)
        RELOAD(5)  RELOAD(6)  RELOAD(7)  RELOAD(8)  RELOAD(9)
        RELOAD(10) RELOAD(11) RELOAD(12) RELOAD(13) RELOAD(14)
        RELOAD(15) RELOAD(16) RELOAD(17) RELOAD(18) RELOAD(19)
        #undef RELOAD

        const int tp1 = t + 1;
        if (tp1 == len0) { float* d = g_hout + (size_t)s0 * NH; SNAP(hA, lo_, d); }
        if (tp1 == len1) { float* d = g_hout + (size_t)s1 * NH; SNAP(hA, hi_, d); }
        if (tp1 == len2) { float* d = g_hout + (size_t)s2 * NH; SNAP(hB, lo_, d); }
        if (tp1 == len3) { float* d = g_hout + (size_t)s3 * NH; SNAP(hB, hi_, d); }

        xA0 = nA0; xA1 = nA1; xA2 = nA2;
        xB0 = nB0; xB1 = nB1; xB2 = nB2;
    }
}

// ---------------- conv + FC kernel ------------------------------------------------
#define C1OUT 46
#define C2OUT 22
#define C3OUT 19

__global__ void __launch_bounds__(128)
k_conv(const int* __restrict__ lengths,
       const float* __restrict__ w_lin, const float* __restrict__ b_lin,
       const float* __restrict__ c1_w, const float* __restrict__ c1_b,
       const float* __restrict__ c2_w, const float* __restrict__ c2_b,
       const float* __restrict__ c3_w, const float* __restrict__ c3_b,
       const float* __restrict__ fc1_w, const float* __restrict__ fc1_b,
       const float* __restrict__ fc2_w, const float* __restrict__ fc2_b,
       float* __restrict__ out)
{
    __shared__ float sbuf[10272];
    __shared__ float sh[NL * NH];
    __shared__ float swl[NO * NH];
    __shared__ float sbl[NO];
    __shared__ int   slen[NL];
    __shared__ float sfc[16];

    float* feat = sbuf;
    float* w1   = sbuf + 800;
    float* y1   = sbuf + 3360;
    float* w2   = sbuf + 4832;
    float* y2   = sbuf + 8928;
    float* y3   = sbuf + 9632;
    float* w3   = sbuf;   // reuse after conv2

    const int b   = blockIdx.x;
    const int tid = threadIdx.x;

    if (tid < NL) slen[tid] = lengths[b * NL + tid];
    for (int i = tid; i < NO * NH; i += 128) swl[i] = w_lin[i];
    if (tid < NO) sbl[tid] = b_lin[tid];
    __syncthreads();
    for (int i = tid; i < NL * NH; i += 128) {
        int l = i / NH, k = i % NH;
        sh[i] = (slen[l] > 0) ? g_hout[(size_t)(b * NL + l) * NH + k] : 0.0f;
    }
    for (int i = tid; i < 2560; i += 128) w1[i] = c1_w[i];
    for (int i = tid; i < 4096; i += 128) w2[i] = c2_w[i];
    __syncthreads();

    for (int i = tid; i < NO * NL; i += 128) {
        int c = i / NL, l = i % NL;
        float s = sbl[c];
        #pragma unroll
        for (int k = 0; k < NH; ++k) s += sh[l * NH + k] * swl[c * NH + k];
        feat[c * NL + l] = (slen[l] > 0) ? fsig(s) : 0.0f;
    }
    __syncthreads();

    for (int idx = tid; idx < 32 * 12; idx += 128) {
        int o = idx / 12, pg = idx % 12, pp = pg * 4;
        float a0 = c1_b[o], a1 = a0, a2 = a0, a3 = a0;
        #pragma unroll
        for (int c = 0; c < 16; ++c) {
            const float* f = feat + c * 50 + pp;
            const float* w = w1 + (o * 16 + c) * 5;
            float wv0 = w[0], wv1 = w[1], wv2 = w[2], wv3 = w[3], wv4 = w[4];
            float f0 = f[0], f1 = f[1], f2 = f[2], f3 = f[3];
            float f4 = f[4], f5 = f[5], f6 = f[6], f7 = f[7];
            a0 += f0*wv0 + f1*wv1 + f2*wv2 + f3*wv3 + f4*wv4;
            a1 += f1*wv0 + f2*wv1 + f3*wv2 + f4*wv3 + f5*wv4;
            a2 += f2*wv0 + f3*wv1 + f4*wv2 + f5*wv3 + f6*wv4;
            a3 += f3*wv0 + f4*wv1 + f5*wv2 + f6*wv3 + f7*wv4;
        }
        if (pp + 0 < C1OUT) y1[o * C1OUT + pp + 0] = fmaxf(a0, 0.0f);
        if (pp + 1 < C1OUT) y1[o * C1OUT + pp + 1] = fmaxf(a1, 0.0f);
        if (pp + 2 < C1OUT) y1[o * C1OUT + pp + 2] = fmaxf(a2, 0.0f);
        if (pp + 3 < C1OUT) y1[o * C1OUT + pp + 3] = fmaxf(a3, 0.0f);
    }
    __syncthreads();

    for (int idx = tid; idx < 32 * 6; idx += 128) {
        int o = idx / 6, pg = idx % 6, pp = pg * 4;
        float a0 = c2_b[o], a1 = a0, a2 = a0, a3 = a0;
        #pragma unroll
        for (int c = 0; c < 32; ++c) {
            const float* f = y1 + c * C1OUT + 2 * pp;
            const float* w = w2 + (o * 32 + c) * 4;
            float wv0 = w[0], wv1 = w[1], wv2 = w[2], wv3 = w[3];
            float f0 = f[0], f1 = f[1], f2 = f[2], f3 = f[3], f4 = f[4];
            float f5 = f[5], f6 = f[6], f7 = f[7], f8 = f[8], f9 = f[9];
            a0 += f0*wv0 + f1*wv1 + f2*wv2 + f3*wv3;
            a1 += f2*wv0 + f3*wv1 + f4*wv2 + f5*wv3;
            a2 += f4*wv0 + f5*wv1 + f6*wv2 + f7*wv3;
            a3 += f6*wv0 + f7*wv1 + f8*wv2 + f9*wv3;
        }
        if (pp + 0 < C2OUT) y2[o * C2OUT + pp + 0] = fmaxf(a0, 0.0f);
        if (pp + 1 < C2OUT) y2[o * C2OUT + pp + 1] = fmaxf(a1, 0.0f);
        if (pp + 2 < C2OUT) y2[o * C2OUT + pp + 2] = fmaxf(a2, 0.0f);
        if (pp + 3 < C2OUT) y2[o * C2OUT + pp + 3] = fmaxf(a3, 0.0f);
    }
    __syncthreads();

    for (int i = tid; i < 4096; i += 128) w3[i] = c3_w[i];
    __syncthreads();

    for (int idx = tid; idx < 32 * 5; idx += 128) {
        int o = idx / 5, pg = idx % 5, pp = pg * 4;
        float a0 = c3_b[o], a1 = a0, a2 = a0, a3 = a0;
        #pragma unroll
        for (int c = 0; c < 32; ++c) {
            const float* f = y2 + c * C2OUT + pp;
            const float* w = w3 + (o * 32 + c) * 4;
            float wv0 = w[0], wv1 = w[1], wv2 = w[2], wv3 = w[3];
            float f0 = f[0], f1 = f[1], f2 = f[2], f3 = f[3];
            float f4 = f[4], f5 = f[5], f6 = f[6];
            a0 += f0*wv0 + f1*wv1 + f2*wv2 + f3*wv3;
            a1 += f1*wv0 + f2*wv1 + f3*wv2 + f4*wv3;
            a2 += f2*wv0 + f3*wv1 + f4*wv2 + f5*wv3;
            a3 += f3*wv0 + f4*wv1 + f5*wv2 + f6*wv3;
        }
        if (pp + 0 < C3OUT) y3[o * C3OUT + pp + 0] = fmaxf(a0, 0.0f);
        if (pp + 1 < C3OUT) y3[o * C3OUT + pp + 1] = fmaxf(a1, 0.0f);
        if (pp + 2 < C3OUT) y3[o * C3OUT + pp + 2] = fmaxf(a2, 0.0f);
        if (pp + 3 < C3OUT) y3[o * C3OUT + pp + 3] = fmaxf(a3, 0.0f);
    }
    __syncthreads();

    {
        const int wd = tid >> 5, lane = tid & 31;
        for (int o = wd; o < 16; o += 4) {
            float a = 0.0f;
            const float* w = fc1_w + o * 608;
            for (int k = lane; k < 608; k += 32) a += y3[k] * w[k];
            #pragma unroll
            for (int s = 16; s > 0; s >>= 1) a += __shfl_xor_sync(0xffffffffu, a, s);
            if (lane == 0) sfc[o] = fmaxf(a + fc1_b[o], 0.0f);
        }
    }
    __syncthreads();

    if (tid < 4) {
        float a = fc2_b[tid];
        #pragma unroll
        for (int k = 0; k < 16; ++k) a += sfc[k] * fc2_w[tid * 16 + k];
        out[(size_t)b * 4 + tid] = a;
    }
}

// ---------------- launch ----------------------------------------------------------
extern "C" void kernel_launch(void* const* d_in, const int* in_sizes, int n_in,
                              void* d_out, int out_size)
{
    const float* x       = (const float*)d_in[0];
    const int*   lengths = (const int*)  d_in[1];
    const float* w_ih    = (const float*)d_in[2];
    const float* w_hh    = (const float*)d_in[3];
    const float* b_ih    = (const float*)d_in[4];
    const float* b_hh    = (const float*)d_in[5];
    const float* w_lin   = (const float*)d_in[6];
    const float* b_lin   = (const float*)d_in[7];
    const float* c1_w    = (const float*)d_in[8];
    const float* c1_b    = (const float*)d_in[9];
    const float* c2_w    = (const float*)d_in[10];
    const float* c2_b    = (const float*)d_in[11];
    const float* c3_w    = (const float*)d_in[12];
    const float* c3_b    = (const float*)d_in[13];
    const float* fc1_w   = (const float*)d_in[14];
    const float* fc1_b   = (const float*)d_in[15];
    const float* fc2_w   = (const float*)d_in[16];
    const float* fc2_b   = (const float*)d_in[17];
    float* out = (float*)d_out;

    k_hist<<<(NSEQ + 255) / 256, 256>>>(lengths);
    k_scan<<<1, 64>>>();
    k_scatter<<<(NSEQ + 255) / 256, 256>>>(lengths);

    k_lstm<<<NCTA_L, TPB>>>(x, lengths, w_ih, w_hh, b_ih, b_hh);

    k_conv<<<NB, 128>>>(lengths, w_lin, b_lin, c1_w, c1_b, c2_w, c2_b, c3_w, c3_b,
                        fc1_w, fc1_b, fc2_w, fc2_b, out);
}

// round 17
// speedup vs baseline: 1.0315x; 1.0045x over previous
#include <cuda_runtime.h>
#include <cstdint>
#include <math.h>

typedef unsigned long long u64;

#define NB   4096
#define NL   50
#define NT   64
#define NF   3
#define NH   20
#define NG   80
#define NO   16
#define NSEQ (NB*NL)        // 204800
#define TPB  64
#define NQUAD (NSEQ/4)      // 51200
#define NCTA_L (NQUAD/TPB)  // 800

// ---------------- device scratch (static; zero-initialized at load) -------------
__device__ int   g_hist[64];
__device__ int   g_off[64];
__device__ int   g_order[NSEQ];
__device__ float g_hout[(size_t)NSEQ * NH];

// ---------------- packed f32x2 helpers ------------------------------------------
__device__ __forceinline__ u64 f2pack(float lo, float hi) {
    u64 r; asm("mov.b64 %0, {%1, %2};" : "=l"(r) : "f"(lo), "f"(hi)); return r;
}
__device__ __forceinline__ void f2unpack(u64 v, float& lo, float& hi) {
    asm("mov.b64 {%0, %1}, %2;" : "=f"(lo), "=f"(hi) : "l"(v));
}
__device__ __forceinline__ u64 ffma2(u64 a, u64 b, u64 c) {
    u64 d; asm("fma.rn.f32x2 %0, %1, %2, %3;" : "=l"(d) : "l"(a), "l"(b), "l"(c)); return d;
}
__device__ __forceinline__ u64 mul2(u64 a, u64 b) {
    u64 r; asm("mul.rn.f32x2 %0, %1, %2;" : "=l"(r) : "l"(a), "l"(b)); return r;
}
__device__ __forceinline__ float tanhaf(float a) {
    float r; asm("tanh.approx.f32 %0, %1;" : "=f"(r) : "f"(a)); return r;
}
// packed tanh: 2 scalar MUFU.TANH
__device__ __forceinline__ u64 tanh2(u64 a) {
    float a0, a1; f2unpack(a, a0, a1);
    return f2pack(tanhaf(a0), tanhaf(a1));
}

// accurate sigmoid (conv stage only)
__device__ __forceinline__ float fsig(float v) {
    return __fdividef(1.0f, 1.0f + __expf(-v));
}

// ---------------- counting sort, descending length, 3 launches -------------------
__global__ void k_hist(const int* __restrict__ lengths) {
    __shared__ int sh[64];
    if (threadIdx.x < 64) sh[threadIdx.x] = 0;
    __syncthreads();
    int i = blockIdx.x * 256 + threadIdx.x;
    if (i < NSEQ) atomicAdd(&sh[lengths[i] & 63], 1);
    __syncthreads();
    if (threadIdx.x < 64 && sh[threadIdx.x]) atomicAdd(&g_hist[threadIdx.x], sh[threadIdx.x]);
}
__global__ void k_scan() {
    if (threadIdx.x == 0) {
        int acc = 0;
        #pragma unroll
        for (int i = 63; i >= 0; --i) { int v = g_hist[i]; g_off[i] = acc; acc += v; }
    }
    __syncthreads();
    if (threadIdx.x < 64) g_hist[threadIdx.x] = 0;   // deterministic on graph replay
}
__global__ void k_scatter(const int* __restrict__ lengths) {
    __shared__ int sh[64], base[64];
    if (threadIdx.x < 64) sh[threadIdx.x] = 0;
    __syncthreads();
    int i = blockIdx.x * 256 + threadIdx.x, l = 0, r = 0;
    if (i < NSEQ) { l = lengths[i] & 63; r = atomicAdd(&sh[l], 1); }
    __syncthreads();
    if (threadIdx.x < 64) {
        int c = sh[threadIdx.x];
        if (c) base[threadIdx.x] = atomicAdd(&g_off[threadIdx.x], c);
    }
    __syncthreads();
    if (i < NSEQ) g_order[base[l] + r] = i;
}

// ---------------- LSTM: 4 seqs/thread, half-folded weights, MUFU.TANH ------------
#define ACC2(accA, accB, wbase) do {                                           \
    const ulonglong2* wp_ = (const ulonglong2*)(wbase);                        \
    ulonglong2 w_;                                                             \
    w_ = wp_[0];                                                               \
    accA = ffma2(hA0,  w_.x, accA); accB = ffma2(hB0,  w_.x, accB);            \
    accA = ffma2(hA1,  w_.y, accA); accB = ffma2(hB1,  w_.y, accB);            \
    w_ = wp_[1];                                                               \
    accA = ffma2(hA2,  w_.x, accA); accB = ffma2(hB2,  w_.x, accB);            \
    accA = ffma2(hA3,  w_.y, accA); accB = ffma2(hB3,  w_.y, accB);            \
    w_ = wp_[2];                                                               \
    accA = ffma2(hA4,  w_.x, accA); accB = ffma2(hB4,  w_.x, accB);            \
    accA = ffma2(hA5,  w_.y, accA); accB = ffma2(hB5,  w_.y, accB);            \
    w_ = wp_[3];                                                               \
    accA = ffma2(hA6,  w_.x, accA); accB = ffma2(hB6,  w_.x, accB);            \
    accA = ffma2(hA7,  w_.y, accA); accB = ffma2(hB7,  w_.y, accB);            \
    w_ = wp_[4];                                                               \
    accA = ffma2(hA8,  w_.x, accA); accB = ffma2(hB8,  w_.x, accB);            \
    accA = ffma2(hA9,  w_.y, accA); accB = ffma2(hB9,  w_.y, accB);            \
    w_ = wp_[5];                                                               \
    accA = ffma2(hA10, w_.x, accA); accB = ffma2(hB10, w_.x, accB);            \
    accA = ffma2(hA11, w_.y, accA); accB = ffma2(hB11, w_.y, accB);            \
    w_ = wp_[6];                                                               \
    accA = ffma2(hA12, w_.x, accA); accB = ffma2(hB12, w_.x, accB);            \
    accA = ffma2(hA13, w_.y, accA); accB = ffma2(hB13, w_.y, accB);            \
    w_ = wp_[7];                                                               \
    accA = ffma2(hA14, w_.x, accA); accB = ffma2(hB14, w_.x, accB);            \
    accA = ffma2(hA15, w_.y, accA); accB = ffma2(hB15, w_.y, accB);            \
    w_ = wp_[8];                                                               \
    accA = ffma2(hA16, w_.x, accA); accB = ffma2(hB16, w_.x, accB);            \
    accA = ffma2(hA17, w_.y, accA); accB = ffma2(hB17, w_.y, accB);            \
    w_ = wp_[9];                                                               \
    accA = ffma2(hA18, w_.x, accA); accB = ffma2(hB18, w_.x, accB);            \
    accA = ffma2(hA19, w_.y, accA); accB = ffma2(hB19, w_.y, accB);            \
} while (0)

#define SNAP(P, SEL, dst) do { float lo_, hi_;                                 \
    f2unpack(P##0,  lo_, hi_); (dst)[0]  = SEL;                                \
    f2unpack(P##1,  lo_, hi_); (dst)[1]  = SEL;                                \
    f2unpack(P##2,  lo_, hi_); (dst)[2]  = SEL;                                \
    f2unpack(P##3,  lo_, hi_); (dst)[3]  = SEL;                                \
    f2unpack(P##4,  lo_, hi_); (dst)[4]  = SEL;                                \
    f2unpack(P##5,  lo_, hi_); (dst)[5]  = SEL;                                \
    f2unpack(P##6,  lo_, hi_); (dst)[6]  = SEL;                                \
    f2unpack(P##7,  lo_, hi_); (dst)[7]  = SEL;                                \
    f2unpack(P##8,  lo_, hi_); (dst)[8]  = SEL;                                \
    f2unpack(P##9,  lo_, hi_); (dst)[9]  = SEL;                                \
    f2unpack(P##10, lo_, hi_); (dst)[10] = SEL;                                \
    f2unpack(P##11, lo_, hi_); (dst)[11] = SEL;                                \
    f2unpack(P##12, lo_, hi_); (dst)[12] = SEL;                                \
    f2unpack(P##13, lo_, hi_); (dst)[13] = SEL;                                \
    f2unpack(P##14, lo_, hi_); (dst)[14] = SEL;                                \
    f2unpack(P##15, lo_, hi_); (dst)[15] = SEL;                                \
    f2unpack(P##16, lo_, hi_); (dst)[16] = SEL;                                \
    f2unpack(P##17, lo_, hi_); (dst)[17] = SEL;                                \
    f2unpack(P##18, lo_, hi_); (dst)[18] = SEL;                                \
    f2unpack(P##19, lo_, hi_); (dst)[19] = SEL;                                \
} while (0)

__global__ void __launch_bounds__(TPB)
k_lstm(const float* __restrict__ x, const int* __restrict__ lengths,
       const float* __restrict__ w_ih, const float* __restrict__ w_hh,
       const float* __restrict__ b_ih, const float* __restrict__ b_hh)
{
    __shared__ __align__(16) u64 sWhh2[NH * 4 * NH];       // 12800 B
    __shared__ __align__(16) u64 sC[NH * 16];              //  2560 B
    __shared__ __align__(16) ulonglong2 cbuf[NH * TPB];    // 20480 B
    __shared__ __align__(16) ulonglong2 hnbuf[NH * TPB];   // 20480 B

    const int tid = threadIdx.x;

    // weight folding for MUFU.TANH activations:
    //   sigma(v) = 0.5 + 0.5*tanh(0.5 v)  -> fold 0.5 into i,f,o rows
    //   tanh(v)  -> g rows unchanged
    for (int i = tid; i < NH * 4 * NH; i += TPB) {
        int j = i / 80, g = (i / 20) & 3, k = i % 20;
        float fold = (g == 2) ? 1.0f : 0.5f;
        float w = w_hh[(g * 20 + j) * 20 + k] * fold;
        sWhh2[i] = f2pack(w, w);
    }
    for (int i = tid; i < NH * 16; i += TPB) {
        int j = i >> 4, e = i & 15;
        float w;
        if (e < 4) {
            int r = e * 20 + j;
            float fold = (e == 2) ? 1.0f : 0.5f;
            w = (b_ih[r] + b_hh[r]) * fold;
        } else {
            int g = (e - 4) / 3, k = (e - 4) % 3;
            float fold = (g == 2) ? 1.0f : 0.5f;
            w = w_ih[(g * 20 + j) * 3 + k] * fold;
        }
        sC[i] = f2pack(w, w);
    }
    #pragma unroll
    for (int j = 0; j < NH; ++j) cbuf[j * TPB + tid] = make_ulonglong2(0ull, 0ull);
    __syncthreads();

    const int qid = blockIdx.x * TPB + tid;
    const int s0 = g_order[4 * qid + 0];
    const int s1 = g_order[4 * qid + 1];
    const int s2 = g_order[4 * qid + 2];
    const int s3 = g_order[4 * qid + 3];
    const int len0 = lengths[s0], len1 = lengths[s1];
    const int len2 = lengths[s2], len3 = lengths[s3];
    const int tmax = max(max(len0, len1), max(len2, len3));

    const float* p0 = x + (size_t)s0 * (NT * NF);
    const float* p1 = x + (size_t)s1 * (NT * NF);
    const float* p2 = x + (size_t)s2 * (NT * NF);
    const float* p3 = x + (size_t)s3 * (NT * NF);

    const u64 HALF2 = f2pack(0.5f, 0.5f);

    u64 hA0 = 0, hA1 = 0, hA2 = 0, hA3 = 0, hA4 = 0, hA5 = 0, hA6 = 0, hA7 = 0,
        hA8 = 0, hA9 = 0, hA10 = 0, hA11 = 0, hA12 = 0, hA13 = 0, hA14 = 0,
        hA15 = 0, hA16 = 0, hA17 = 0, hA18 = 0, hA19 = 0;
    u64 hB0 = 0, hB1 = 0, hB2 = 0, hB3 = 0, hB4 = 0, hB5 = 0, hB6 = 0, hB7 = 0,
        hB8 = 0, hB9 = 0, hB10 = 0, hB11 = 0, hB12 = 0, hB13 = 0, hB14 = 0,
        hB15 = 0, hB16 = 0, hB17 = 0, hB18 = 0, hB19 = 0;

    u64 xA0 = 0, xA1 = 0, xA2 = 0, xB0 = 0, xB1 = 0, xB2 = 0;
    if (tmax > 0) {
        xA0 = f2pack(p0[0], p1[0]); xA1 = f2pack(p0[1], p1[1]); xA2 = f2pack(p0[2], p1[2]);
        xB0 = f2pack(p2[0], p3[0]); xB1 = f2pack(p2[1], p3[1]); xB2 = f2pack(p2[2], p3[2]);
    }

    for (int t = 0; t < tmax; ++t) {
        const int tn = t + 1;   // t <= tmax-1 <= 62 in-loop; rows 0..63 always exist
        const u64 nA0 = f2pack(p0[3 * tn + 0], p1[3 * tn + 0]);
        const u64 nA1 = f2pack(p0[3 * tn + 1], p1[3 * tn + 1]);
        const u64 nA2 = f2pack(p0[3 * tn + 2], p1[3 * tn + 2]);
        const u64 nB0 = f2pack(p2[3 * tn + 0], p3[3 * tn + 0]);
        const u64 nB1 = f2pack(p2[3 * tn + 1], p3[3 * tn + 1]);
        const u64 nB2 = f2pack(p2[3 * tn + 2], p3[3 * tn + 2]);

        #pragma unroll 2
        for (int j = 0; j < NH; ++j) {
            const ulonglong2* cb_ = (const ulonglong2*)(sC + j * 16);
            const ulonglong2 b01 = cb_[0], b23 = cb_[1];
            const ulonglong2 wa = cb_[2], wb = cb_[3], wc = cb_[4];
            const ulonglong2 wd = cb_[5], we = cb_[6], wf = cb_[7];

            u64 aiA = b01.x, afA = b01.y, agA = b23.x, aoA = b23.y;
            u64 aiB = b01.x, afB = b01.y, agB = b23.x, aoB = b23.y;

            aiA = ffma2(xA0, wa.x, aiA); aiB = ffma2(xB0, wa.x, aiB);
            aiA = ffma2(xA1, wa.y, aiA); aiB = ffma2(xB1, wa.y, aiB);
            aiA = ffma2(xA2, wb.x, aiA); aiB = ffma2(xB2, wb.x, aiB);
            afA = ffma2(xA0, wb.y, afA); afB = ffma2(xB0, wb.y, afB);
            afA = ffma2(xA1, wc.x, afA); afB = ffma2(xB1, wc.x, afB);
            afA = ffma2(xA2, wc.y, afA); afB = ffma2(xB2, wc.y, afB);
            agA = ffma2(xA0, wd.x, agA); agB = ffma2(xB0, wd.x, agB);
            agA = ffma2(xA1, wd.y, agA); agB = ffma2(xB1, wd.y, agB);
            agA = ffma2(xA2, we.x, agA); agB = ffma2(xB2, we.x, agB);
            aoA = ffma2(xA0, we.y, aoA); aoB = ffma2(xB0, we.y, aoB);
            aoA = ffma2(xA1, wf.x, aoA); aoB = ffma2(xB1, wf.x, aoB);
            aoA = ffma2(xA2, wf.y, aoA); aoB = ffma2(xB2, wf.y, aoB);

            ACC2(aiA, aiB, sWhh2 + j * 80);
            ACC2(afA, afB, sWhh2 + j * 80 + 20);
            ACC2(agA, agB, sWhh2 + j * 80 + 40);
            ACC2(aoA, aoB, sWhh2 + j * 80 + 60);

            const ulonglong2 cold = cbuf[j * TPB + tid];
            ulonglong2 cnew, hnew;

            // pack A: sigma = 0.5 + 0.5*tanh(folded), tanh direct (MUFU.TANH)
            {
                u64 si = ffma2(tanh2(aiA), HALF2, HALF2);
                u64 sf = ffma2(tanh2(afA), HALF2, HALF2);
                u64 tg = tanh2(agA);
                u64 so = ffma2(tanh2(aoA), HALF2, HALF2);
                u64 cn = ffma2(sf, cold.x, mul2(si, tg));
                cnew.x = cn;
                hnew.x = mul2(so, tanh2(cn));
            }
            // pack B
            {
                u64 si = ffma2(tanh2(aiB), HALF2, HALF2);
                u64 sf = ffma2(tanh2(afB), HALF2, HALF2);
                u64 tg = tanh2(agB);
                u64 so = ffma2(tanh2(aoB), HALF2, HALF2);
                u64 cn = ffma2(sf, cold.y, mul2(si, tg));
                cnew.y = cn;
                hnew.y = mul2(so, tanh2(cn));
            }

            cbuf[j * TPB + tid]  = cnew;
            hnbuf[j * TPB + tid] = hnew;
        }

        // commit h from staging into named regs
        #define RELOAD(k) { ulonglong2 v_ = hnbuf[(k) * TPB + tid]; hA##k = v_.x; hB##k = v_.y; }
        RELOAD(0)  RELOAD(1)  RELOAD(2)  RELOAD(3)  RELOAD(4)
        RELOAD(5)  RELOAD(6)  RELOAD(7)  RELOAD(8)  RELOAD(9)
        RELOAD(10) RELOAD(11) RELOAD(12) RELOAD(13) RELOAD(14)
        RELOAD(15) RELOAD(16) RELOAD(17) RELOAD(18) RELOAD(19)
        #undef RELOAD

        // snapshot final h when a sequence completes: ONE combined guard
        // (single BSSY region per step instead of four; arms rarely taken)
        const int tp1 = t + 1;
        const int hit = (tp1 == len0) | (tp1 == len1) | (tp1 == len2) | (tp1 == len3);
        if (hit) {
            if (tp1 == len0) { float* d = g_hout + (size_t)s0 * NH; SNAP(hA, lo_, d); }
            if (tp1 == len1) { float* d = g_hout + (size_t)s1 * NH; SNAP(hA, hi_, d); }
            if (tp1 == len2) { float* d = g_hout + (size_t)s2 * NH; SNAP(hB, lo_, d); }
            if (tp1 == len3) { float* d = g_hout + (size_t)s3 * NH; SNAP(hB, hi_, d); }
        }

        xA0 = nA0; xA1 = nA1; xA2 = nA2;
        xB0 = nB0; xB1 = nB1; xB2 = nB2;
    }
}

// ---------------- conv + FC kernel ------------------------------------------------
#define C1OUT 46
#define C2OUT 22
#define C3OUT 19

__global__ void __launch_bounds__(128)
k_conv(const int* __restrict__ lengths,
       const float* __restrict__ w_lin, const float* __restrict__ b_lin,
       const float* __restrict__ c1_w, const float* __restrict__ c1_b,
       const float* __restrict__ c2_w, const float* __restrict__ c2_b,
       const float* __restrict__ c3_w, const float* __restrict__ c3_b,
       const float* __restrict__ fc1_w, const float* __restrict__ fc1_b,
       const float* __restrict__ fc2_w, const float* __restrict__ fc2_b,
       float* __restrict__ out)
{
    __shared__ float sbuf[10272];
    __shared__ float sh[NL * NH];
    __shared__ float swl[NO * NH];
    __shared__ float sbl[NO];
    __shared__ int   slen[NL];
    __shared__ float sfc[16];

    float* feat = sbuf;
    float* w1   = sbuf + 800;
    float* y1   = sbuf + 3360;
    float* w2   = sbuf + 4832;
    float* y2   = sbuf + 8928;
    float* y3   = sbuf + 9632;
    float* w3   = sbuf;   // reuse after conv2

    const int b   = blockIdx.x;
    const int tid = threadIdx.x;

    if (tid < NL) slen[tid] = lengths[b * NL + tid];
    for (int i = tid; i < NO * NH; i += 128) swl[i] = w_lin[i];
    if (tid < NO) sbl[tid] = b_lin[tid];
    __syncthreads();
    for (int i = tid; i < NL * NH; i += 128) {
        int l = i / NH, k = i % NH;
        sh[i] = (slen[l] > 0) ? g_hout[(size_t)(b * NL + l) * NH + k] : 0.0f;
    }
    for (int i = tid; i < 2560; i += 128) w1[i] = c1_w[i];
    for (int i = tid; i < 4096; i += 128) w2[i] = c2_w[i];
    __syncthreads();

    for (int i = tid; i < NO * NL; i += 128) {
        int c = i / NL, l = i % NL;
        float s = sbl[c];
        #pragma unroll
        for (int k = 0; k < NH; ++k) s += sh[l * NH + k] * swl[c * NH + k];
        feat[c * NL + l] = (slen[l] > 0) ? fsig(s) : 0.0f;
    }
    __syncthreads();

    for (int idx = tid; idx < 32 * 12; idx += 128) {
        int o = idx / 12, pg = idx % 12, pp = pg * 4;
        float a0 = c1_b[o], a1 = a0, a2 = a0, a3 = a0;
        #pragma unroll
        for (int c = 0; c < 16; ++c) {
            const float* f = feat + c * 50 + pp;
            const float* w = w1 + (o * 16 + c) * 5;
            float wv0 = w[0], wv1 = w[1], wv2 = w[2], wv3 = w[3], wv4 = w[4];
            float f0 = f[0], f1 = f[1], f2 = f[2], f3 = f[3];
            float f4 = f[4], f5 = f[5], f6 = f[6], f7 = f[7];
            a0 += f0*wv0 + f1*wv1 + f2*wv2 + f3*wv3 + f4*wv4;
            a1 += f1*wv0 + f2*wv1 + f3*wv2 + f4*wv3 + f5*wv4;
            a2 += f2*wv0 + f3*wv1 + f4*wv2 + f5*wv3 + f6*wv4;
            a3 += f3*wv0 + f4*wv1 + f5*wv2 + f6*wv3 + f7*wv4;
        }
        if (pp + 0 < C1OUT) y1[o * C1OUT + pp + 0] = fmaxf(a0, 0.0f);
        if (pp + 1 < C1OUT) y1[o * C1OUT + pp + 1] = fmaxf(a1, 0.0f);
        if (pp + 2 < C1OUT) y1[o * C1OUT + pp + 2] = fmaxf(a2, 0.0f);
        if (pp + 3 < C1OUT) y1[o * C1OUT + pp + 3] = fmaxf(a3, 0.0f);
    }
    __syncthreads();

    for (int idx = tid; idx < 32 * 6; idx += 128) {
        int o = idx / 6, pg = idx % 6, pp = pg * 4;
        float a0 = c2_b[o], a1 = a0, a2 = a0, a3 = a0;
        #pragma unroll
        for (int c = 0; c < 32; ++c) {
            const float* f = y1 + c * C1OUT + 2 * pp;
            const float* w = w2 + (o * 32 + c) * 4;
            float wv0 = w[0], wv1 = w[1], wv2 = w[2], wv3 = w[3];
            float f0 = f[0], f1 = f[1], f2 = f[2], f3 = f[3], f4 = f[4];
            float f5 = f[5], f6 = f[6], f7 = f[7], f8 = f[8], f9 = f[9];
            a0 += f0*wv0 + f1*wv1 + f2*wv2 + f3*wv3;
            a1 += f2*wv0 + f3*wv1 + f4*wv2 + f5*wv3;
            a2 += f4*wv0 + f5*wv1 + f6*wv2 + f7*wv3;
            a3 += f6*wv0 + f7*wv1 + f8*wv2 + f9*wv3;
        }
        if (pp + 0 < C2OUT) y2[o * C2OUT + pp + 0] = fmaxf(a0, 0.0f);
        if (pp + 1 < C2OUT) y2[o * C2OUT + pp + 1] = fmaxf(a1, 0.0f);
        if (pp + 2 < C2OUT) y2[o * C2OUT + pp + 2] = fmaxf(a2, 0.0f);
        if (pp + 3 < C2OUT) y2[o * C2OUT + pp + 3] = fmaxf(a3, 0.0f);
    }
    __syncthreads();

    for (int i = tid; i < 4096; i += 128) w3[i] = c3_w[i];
    __syncthreads();

    for (int idx = tid; idx < 32 * 5; idx += 128) {
        int o = idx / 5, pg = idx % 5, pp = pg * 4;
        float a0 = c3_b[o], a1 = a0, a2 = a0, a3 = a0;
        #pragma unroll
        for (int c = 0; c < 32; ++c) {
            const float* f = y2 + c * C2OUT + pp;
            const float* w = w3 + (o * 32 + c) * 4;
            float wv0 = w[0], wv1 = w[1], wv2 = w[2], wv3 = w[3];
            float f0 = f[0], f1 = f[1], f2 = f[2], f3 = f[3];
            float f4 = f[4], f5 = f[5], f6 = f[6];
            a0 += f0*wv0 + f1*wv1 + f2*wv2 + f3*wv3;
            a1 += f1*wv0 + f2*wv1 + f3*wv2 + f4*wv3;
            a2 += f2*wv0 + f3*wv1 + f4*wv2 + f5*wv3;
            a3 += f3*wv0 + f4*wv1 + f5*wv2 + f6*wv3;
        }
        if (pp + 0 < C3OUT) y3[o * C3OUT + pp + 0] = fmaxf(a0, 0.0f);
        if (pp + 1 < C3OUT) y3[o * C3OUT + pp + 1] = fmaxf(a1, 0.0f);
        if (pp + 2 < C3OUT) y3[o * C3OUT + pp + 2] = fmaxf(a2, 0.0f);
        if (pp + 3 < C3OUT) y3[o * C3OUT + pp + 3] = fmaxf(a3, 0.0f);
    }
    __syncthreads();

    {
        const int wd = tid >> 5, lane = tid & 31;
        for (int o = wd; o < 16; o += 4) {
            float a = 0.0f;
            const float* w = fc1_w + o * 608;
            for (int k = lane; k < 608; k += 32) a += y3[k] * w[k];
            #pragma unroll
            for (int s = 16; s > 0; s >>= 1) a += __shfl_xor_sync(0xffffffffu, a, s);
            if (lane == 0) sfc[o] = fmaxf(a + fc1_b[o], 0.0f);
        }
    }
    __syncthreads();

    if (tid < 4) {
        float a = fc2_b[tid];
        #pragma unroll
        for (int k = 0; k < 16; ++k) a += sfc[k] * fc2_w[tid * 16 + k];
        out[(size_t)b * 4 + tid] = a;
    }
}

// ---------------- launch ----------------------------------------------------------
extern "C" void kernel_launch(void* const* d_in, const int* in_sizes, int n_in,
                              void* d_out, int out_size)
{
    const float* x       = (const float*)d_in[0];
    const int*   lengths = (const int*)  d_in[1];
    const float* w_ih    = (const float*)d_in[2];
    const float* w_hh    = (const float*)d_in[3];
    const float* b_ih    = (const float*)d_in[4];
    const float* b_hh    = (const float*)d_in[5];
    const float* w_lin   = (const float*)d_in[6];
    const float* b_lin   = (const float*)d_in[7];
    const float* c1_w    = (const float*)d_in[8];
    const float* c1_b    = (const float*)d_in[9];
    const float* c2_w    = (const float*)d_in[10];
    const float* c2_b    = (const float*)d_in[11];
    const float* c3_w    = (const float*)d_in[12];
    const float* c3_b    = (const float*)d_in[13];
    const float* fc1_w   = (const float*)d_in[14];
    const float* fc1_b   = (const float*)d_in[15];
    const float* fc2_w   = (const float*)d_in[16];
    const float* fc2_b   = (const float*)d_in[17];
    float* out = (float*)d_out;

    k_hist<<<(NSEQ + 255) / 256, 256>>>(lengths);
    k_scan<<<1, 64>>>();
    k_scatter<<<(NSEQ + 255) / 256, 256>>>(lengths);

    k_lstm<<<NCTA_L, TPB>>>(x, lengths, w_ih, w_hh, b_ih, b_hh);

    k_conv<<<NB, 128>>>(lengths, w_lin, b_lin, c1_w, c1_b, c2_w, c2_b, c3_w, c3_b,
                        fc1_w, fc1_b, fc2_w, fc2_b, out);
}